// round 1
// baseline (speedup 1.0000x reference)
#include <cuda_runtime.h>
#include <math.h>

#define BATCH 4
#define SEQ 2048
#define CH 768
#define NHEADS 12
#define HD 64
#define MTOT (BATCH * SEQ)   // 8192
#define C3 (3 * CH)          // 2304

// Scratch (allocation-free contract): qkv projection output + attention output
__device__ float g_qkv[(size_t)MTOT * C3];   // ~75.5 MB
__device__ float g_att[(size_t)MTOT * CH];   // ~25 MB

// ---------------------------------------------------------------------------
// Generic tiled fp32 GEMM with bias: C[M,N] = A[M,K] @ B[K,N] + bias[N]
// 64x64 block tile, K-tile 16, 256 threads, 4x4 per-thread micro-tile.
// Requires M%64==0, N%64==0, K%16==0 (holds for all three calls).
// ---------------------------------------------------------------------------
__global__ __launch_bounds__(256) void gemm_bias_kernel(
    const float* __restrict__ A, const float* __restrict__ B,
    const float* __restrict__ bias, float* __restrict__ C,
    int M, int N, int K)
{
    __shared__ float As[16][68];   // padded: transposed store -> 2-way not 16-way
    __shared__ float Bs[16][64];
    const int tid = threadIdx.x;
    const int tx = tid & 15, ty = tid >> 4;
    const int bm = blockIdx.y * 64, bn = blockIdx.x * 64;

    float acc[4][4] = {};

    for (int k0 = 0; k0 < K; k0 += 16) {
        #pragma unroll
        for (int i = 0; i < 4; i++) {
            int idx = tid + i * 256;            // 1024 elems of A tile
            int m = idx >> 4, kk = idx & 15;    // coalesced gmem read over kk
            As[kk][m] = A[(long)(bm + m) * K + k0 + kk];
        }
        #pragma unroll
        for (int i = 0; i < 4; i++) {
            int idx = tid + i * 256;            // 1024 elems of B tile
            int kk = idx >> 6, n = idx & 63;    // coalesced gmem read over n
            Bs[kk][n] = B[(long)(k0 + kk) * N + bn + n];
        }
        __syncthreads();

        #pragma unroll
        for (int kk = 0; kk < 16; kk++) {
            float a[4], b[4];
            #pragma unroll
            for (int r = 0; r < 4; r++) a[r] = As[kk][ty * 4 + r];
            #pragma unroll
            for (int c = 0; c < 4; c++) b[c] = Bs[kk][tx * 4 + c];
            #pragma unroll
            for (int r = 0; r < 4; r++)
                #pragma unroll
                for (int c = 0; c < 4; c++)
                    acc[r][c] = fmaf(a[r], b[c], acc[r][c]);
        }
        __syncthreads();
    }

    #pragma unroll
    for (int r = 0; r < 4; r++) {
        const long row = bm + ty * 4 + r;
        #pragma unroll
        for (int c = 0; c < 4; c++) {
            const int col = bn + tx * 4 + c;
            C[row * N + col] = acc[r][c] + bias[col];
        }
    }
}

// ---------------------------------------------------------------------------
// Flash attention, fp32 SIMT. One block = one (b, h, 64-row query tile).
// Streams over KV in 64-row tiles with online softmax. Scores never hit HBM.
// K/P buffer is XOR-swizzled to avoid 16-way LDS conflicts on column reads.
// ---------------------------------------------------------------------------
__global__ __launch_bounds__(256) void flash_attn_kernel()
{
    __shared__ float Qs[64][64];
    __shared__ float KPs[64 * 64];   // K tile, reused as P tile
    __shared__ float Vs[64][64];
    // swizzle: row r, logical col d stored at d ^ (r & 31)  (bijective per row)
    #define KP(r, d) KPs[(((r) << 6)) | (((d) ^ ((r) & 31)))]

    const int tid = threadIdx.x;
    const int tx = tid & 15, ty = tid >> 4;
    const int b = blockIdx.y / NHEADS, h = blockIdx.y % NHEADS;
    const int q0 = blockIdx.x * 64;
    const int rowbase = b * SEQ;
    const float scale = 0.125f;   // 1/sqrt(64)

    // Load Q tile (coalesced)
    for (int i = tid; i < 64 * 64; i += 256) {
        int r = i >> 6, d = i & 63;
        Qs[r][d] = g_qkv[(rowbase + q0 + r) * C3 + h * HD + d];
    }

    float m_i[4], l_i[4], O[4][4];
    #pragma unroll
    for (int r = 0; r < 4; r++) {
        m_i[r] = -1e30f; l_i[r] = 0.f;
        #pragma unroll
        for (int c = 0; c < 4; c++) O[r][c] = 0.f;
    }

    for (int k0 = 0; k0 < SEQ; k0 += 64) {
        __syncthreads();   // also covers Q-load on first iter, PV reads on later iters
        for (int i = tid; i < 64 * 64; i += 256) {
            int r = i >> 6, d = i & 63;
            int base = (rowbase + k0 + r) * C3 + h * HD + d;
            KP(r, d) = g_qkv[base + CH];        // K
            Vs[r][d] = g_qkv[base + 2 * CH];    // V
        }
        __syncthreads();

        // S = Q @ K^T  (4x4 per thread over 64 k-steps)
        float s[4][4] = {};
        #pragma unroll 8
        for (int kk = 0; kk < 64; kk++) {
            float a[4], bb[4];
            #pragma unroll
            for (int r = 0; r < 4; r++) a[r] = Qs[ty * 4 + r][kk];
            #pragma unroll
            for (int c = 0; c < 4; c++) bb[c] = KP(tx * 4 + c, kk);
            #pragma unroll
            for (int r = 0; r < 4; r++)
                #pragma unroll
                for (int c = 0; c < 4; c++)
                    s[r][c] = fmaf(a[r], bb[c], s[r][c]);
        }

        // Online softmax update. Row is spread over 16 tx-lanes (half-warp),
        // so xor-shuffles with offsets 8,4,2,1 reduce within the row group.
        float p[4][4];
        #pragma unroll
        for (int r = 0; r < 4; r++) {
            float mx = -1e30f;
            #pragma unroll
            for (int c = 0; c < 4; c++) {
                s[r][c] *= scale;
                mx = fmaxf(mx, s[r][c]);
            }
            #pragma unroll
            for (int off = 8; off > 0; off >>= 1)
                mx = fmaxf(mx, __shfl_xor_sync(0xffffffffu, mx, off));
            float mnew = fmaxf(m_i[r], mx);
            float corr = __expf(m_i[r] - mnew);
            float rs = 0.f;
            #pragma unroll
            for (int c = 0; c < 4; c++) {
                p[r][c] = __expf(s[r][c] - mnew);
                rs += p[r][c];
            }
            #pragma unroll
            for (int off = 8; off > 0; off >>= 1)
                rs += __shfl_xor_sync(0xffffffffu, rs, off);
            l_i[r] = l_i[r] * corr + rs;
            m_i[r] = mnew;
            #pragma unroll
            for (int c = 0; c < 4; c++) O[r][c] *= corr;
        }

        __syncthreads();   // everyone done reading K from KPs
        #pragma unroll
        for (int r = 0; r < 4; r++)
            #pragma unroll
            for (int c = 0; c < 4; c++)
                KP(ty * 4 + r, tx * 4 + c) = p[r][c];
        __syncthreads();

        // O += P @ V
        #pragma unroll 8
        for (int j = 0; j < 64; j++) {
            float a[4], bb[4];
            #pragma unroll
            for (int r = 0; r < 4; r++) a[r] = KP(ty * 4 + r, j);
            #pragma unroll
            for (int c = 0; c < 4; c++) bb[c] = Vs[j][tx * 4 + c];
            #pragma unroll
            for (int r = 0; r < 4; r++)
                #pragma unroll
                for (int c = 0; c < 4; c++)
                    O[r][c] = fmaf(a[r], bb[c], O[r][c]);
        }
    }

    // Normalize and write (B, N, h*64+d) layout so proj GEMM reads row-major
    #pragma unroll
    for (int r = 0; r < 4; r++) {
        float inv = 1.f / l_i[r];
        #pragma unroll
        for (int c = 0; c < 4; c++)
            g_att[(rowbase + q0 + ty * 4 + r) * CH + h * HD + tx * 4 + c] =
                O[r][c] * inv;
    }
    #undef KP
}

// ---------------------------------------------------------------------------
// Launch: qkv GEMM -> flash attention -> projection GEMM
// ---------------------------------------------------------------------------
extern "C" void kernel_launch(void* const* d_in, const int* in_sizes, int n_in,
                              void* d_out, int out_size)
{
    const float* x     = (const float*)d_in[0];
    const float* Wqkv  = (const float*)d_in[1];
    const float* bqkv  = (const float*)d_in[2];
    const float* Wproj = (const float*)d_in[3];
    const float* bproj = (const float*)d_in[4];
    float* out = (float*)d_out;

    float *qkv_ptr, *att_ptr;
    cudaGetSymbolAddress((void**)&qkv_ptr, g_qkv);
    cudaGetSymbolAddress((void**)&att_ptr, g_att);

    // QKV projection: (8192, 768) @ (768, 2304) + bias
    gemm_bias_kernel<<<dim3(C3 / 64, MTOT / 64), 256>>>(
        x, Wqkv, bqkv, qkv_ptr, MTOT, C3, CH);

    // Flash attention: 32 query tiles x (4 batch * 12 heads)
    flash_attn_kernel<<<dim3(SEQ / 64, BATCH * NHEADS), 256>>>();

    // Output projection: (8192, 768) @ (768, 768) + bias
    gemm_bias_kernel<<<dim3(CH / 64, MTOT / 64), 256>>>(
        att_ptr, Wproj, bproj, out, MTOT, CH, CH);
}

// round 2
// speedup vs baseline: 2.8926x; 2.8926x over previous
#include <cuda_runtime.h>
#include <math.h>

#define BATCH 4
#define SEQ 2048
#define CH 768
#define NHEADS 12
#define HD 64
#define MTOT (BATCH * SEQ)   // 8192
#define C3 (3 * CH)          // 2304

// Scratch (allocation-free contract)
__device__ float g_qkv[(size_t)MTOT * C3];   // ~75.5 MB
__device__ float g_att[(size_t)MTOT * CH];   // ~25 MB

__device__ __forceinline__ unsigned f2tf(float x) {
    unsigned u;
    asm("cvt.rna.tf32.f32 %0, %1;" : "=r"(u) : "f"(x));
    return u;
}

// m16n8k8 tf32 mma, fp32 accumulate in-place.
// A frag: a0=(g,tq) a1=(g+8,tq) a2=(g,tq+4) a3=(g+8,tq+4)   [g=lane>>2, tq=lane&3]
// B frag: b0=(k=tq,n=g) b1=(k=tq+4,n=g)
// C frag: c0=(g,2tq) c1=(g,2tq+1) c2=(g+8,2tq) c3=(g+8,2tq+1)
__device__ __forceinline__ void mma8(float* c, const unsigned* a,
                                     unsigned b0, unsigned b1) {
    asm volatile(
        "mma.sync.aligned.m16n8k8.row.col.f32.tf32.tf32.f32 "
        "{%0,%1,%2,%3}, {%4,%5,%6,%7}, {%8,%9}, {%0,%1,%2,%3};"
        : "+f"(c[0]), "+f"(c[1]), "+f"(c[2]), "+f"(c[3])
        : "r"(a[0]), "r"(a[1]), "r"(a[2]), "r"(a[3]), "r"(b0), "r"(b1));
}

// ---------------------------------------------------------------------------
// tf32 tensor-core GEMM + bias: C[M,N] = A[M,K] @ B[K,N] + bias
// 128x128 block tile, BK=32, 256 threads (8 warps, 4x2), warp tile 32x64.
// Smem pads chosen so all frag LDS are bank-conflict-free (bank == lane).
// Requires M%128==0, N%128==0, K%32==0.
// ---------------------------------------------------------------------------
#define BK 32
__global__ __launch_bounds__(256) void gemm_tf32(
    const float* __restrict__ A, const float* __restrict__ B,
    const float* __restrict__ bias, float* __restrict__ C,
    int M, int N, int K)
{
    __shared__ unsigned As[128][BK + 4];   // pad 36: bank(m*36+k) = lane
    __shared__ unsigned Bt[128][BK + 4];   // B transposed: [n][k]
    const int tid = threadIdx.x;
    const int lane = tid & 31, wid = tid >> 5;
    const int g = lane >> 2, tq = lane & 3;
    const int wm = (wid & 3) * 32, wn = (wid >> 2) * 64;
    const int bm = blockIdx.y * 128, bn = blockIdx.x * 128;

    // Gmem load mapping (per thread 4x float4 for each of A, B)
    const int ar = tid >> 3, ak = (tid & 7) * 4;       // A: row ar+32i, k ak..ak+3
    const int bk = tid >> 5, bn4 = (tid & 31) * 4;     // B: k bk+8i, n bn4..bn4+3
    const float* Ap = A + (long)(bm + ar) * K + ak;
    const float* Bp = B + (long)bk * N + bn + bn4;

    float acc[2][8][4];
    #pragma unroll
    for (int mt = 0; mt < 2; mt++)
        #pragma unroll
        for (int nt = 0; nt < 8; nt++)
            #pragma unroll
            for (int j = 0; j < 4; j++) acc[mt][nt][j] = 0.f;

    float4 ra[4], rb[4], ra2[4], rb2[4];
    #pragma unroll
    for (int i = 0; i < 4; i++) ra[i] = *(const float4*)(Ap + (long)(32 * i) * K);
    #pragma unroll
    for (int i = 0; i < 4; i++) rb[i] = *(const float4*)(Bp + (long)(8 * i) * N);

    const int nk = K / BK;
    for (int kt = 0; kt < nk; kt++) {
        // stage current tile to smem (convert to tf32)
        #pragma unroll
        for (int i = 0; i < 4; i++) {
            unsigned* d = &As[ar + 32 * i][ak];
            d[0] = f2tf(ra[i].x); d[1] = f2tf(ra[i].y);
            d[2] = f2tf(ra[i].z); d[3] = f2tf(ra[i].w);
        }
        #pragma unroll
        for (int i = 0; i < 4; i++) {
            int kk = bk + 8 * i;
            Bt[bn4 + 0][kk] = f2tf(rb[i].x); Bt[bn4 + 1][kk] = f2tf(rb[i].y);
            Bt[bn4 + 2][kk] = f2tf(rb[i].z); Bt[bn4 + 3][kk] = f2tf(rb[i].w);
        }
        __syncthreads();

        // prefetch next tile
        if (kt + 1 < nk) {
            const float* An = Ap + (kt + 1) * BK;
            const float* Bn = Bp + (long)(kt + 1) * BK * N;
            #pragma unroll
            for (int i = 0; i < 4; i++) ra2[i] = *(const float4*)(An + (long)(32 * i) * K);
            #pragma unroll
            for (int i = 0; i < 4; i++) rb2[i] = *(const float4*)(Bn + (long)(8 * i) * N);
        }

        // compute BK=32 (4 k8 steps)
        #pragma unroll
        for (int ks = 0; ks < 4; ks++) {
            const int kb = ks * 8;
            unsigned af[2][4];
            #pragma unroll
            for (int mt = 0; mt < 2; mt++) {
                int r = wm + mt * 16 + g;
                af[mt][0] = As[r][kb + tq];     af[mt][1] = As[r + 8][kb + tq];
                af[mt][2] = As[r][kb + tq + 4]; af[mt][3] = As[r + 8][kb + tq + 4];
            }
            #pragma unroll
            for (int nt = 0; nt < 8; nt++) {
                int c = wn + nt * 8 + g;
                unsigned b0 = Bt[c][kb + tq], b1 = Bt[c][kb + tq + 4];
                mma8(acc[0][nt], af[0], b0, b1);
                mma8(acc[1][nt], af[1], b0, b1);
            }
        }
        __syncthreads();
        #pragma unroll
        for (int i = 0; i < 4; i++) { ra[i] = ra2[i]; rb[i] = rb2[i]; }
    }

    // epilogue
    #pragma unroll
    for (int mt = 0; mt < 2; mt++) {
        const long r0 = bm + wm + mt * 16 + g;
        #pragma unroll
        for (int nt = 0; nt < 8; nt++) {
            const int col = bn + wn + nt * 8 + 2 * tq;
            const float bz0 = bias[col], bz1 = bias[col + 1];
            C[r0 * N + col]           = acc[mt][nt][0] + bz0;
            C[r0 * N + col + 1]       = acc[mt][nt][1] + bz1;
            C[(r0 + 8) * N + col]     = acc[mt][nt][2] + bz0;
            C[(r0 + 8) * N + col + 1] = acc[mt][nt][3] + bz1;
        }
    }
}

// ---------------------------------------------------------------------------
// Flash attention with tf32 mma. Br=Bc=64, d=64, 128 threads (4 warps).
// Warp w owns S/O rows [16w, 16w+16). S and PV both via m16n8k8 mma.
// Dynamic smem: Qs, Ks, Vt, Ps, each 64x68 words (pad 68 -> bank == lane).
// ---------------------------------------------------------------------------
__global__ __launch_bounds__(128) void flash_tf32()
{
    extern __shared__ unsigned sm[];
    unsigned (*Qs)[68] = (unsigned(*)[68])(sm);
    unsigned (*Ks)[68] = (unsigned(*)[68])(sm + 64 * 68);
    unsigned (*Vt)[68] = (unsigned(*)[68])(sm + 2 * 64 * 68);
    unsigned (*Ps)[68] = (unsigned(*)[68])(sm + 3 * 64 * 68);

    const int tid = threadIdx.x;
    const int lane = tid & 31, w = tid >> 5;
    const int g = lane >> 2, tq = lane & 3;
    const int b = blockIdx.y / NHEADS, h = blockIdx.y % NHEADS;
    const int q0 = blockIdx.x * 64;
    const long rowbase = (long)b * SEQ;
    const float scale = 0.125f;

    // Load Q tile (float4, convert to tf32)
    #pragma unroll
    for (int i = 0; i < 8; i++) {
        int idx = tid + 128 * i;
        int r = idx >> 4, c4 = (idx & 15) * 4;
        float4 v = *(const float4*)&g_qkv[(rowbase + q0 + r) * C3 + h * HD + c4];
        unsigned* d = &Qs[r][c4];
        d[0] = f2tf(v.x); d[1] = f2tf(v.y); d[2] = f2tf(v.z); d[3] = f2tf(v.w);
    }

    float o[8][4];
    #pragma unroll
    for (int nt = 0; nt < 8; nt++)
        #pragma unroll
        for (int j = 0; j < 4; j++) o[nt][j] = 0.f;
    float m0 = -1e30f, m1 = -1e30f, l0 = 0.f, l1 = 0.f;

    for (int k0 = 0; k0 < SEQ; k0 += 64) {
        __syncthreads();
        #pragma unroll
        for (int i = 0; i < 8; i++) {
            int idx = tid + 128 * i;
            int r = idx >> 4, c4 = (idx & 15) * 4;
            long gb = (rowbase + k0 + r) * C3 + h * HD + c4;
            float4 kv = *(const float4*)&g_qkv[gb + CH];
            unsigned* d = &Ks[r][c4];
            d[0] = f2tf(kv.x); d[1] = f2tf(kv.y); d[2] = f2tf(kv.z); d[3] = f2tf(kv.w);
            float4 vv = *(const float4*)&g_qkv[gb + 2 * CH];
            Vt[c4 + 0][r] = f2tf(vv.x); Vt[c4 + 1][r] = f2tf(vv.y);
            Vt[c4 + 2][r] = f2tf(vv.z); Vt[c4 + 3][r] = f2tf(vv.w);
        }
        __syncthreads();

        // S = Q @ K^T  (warp rows 16w..16w+15, all 64 kv cols)
        float s[8][4];
        #pragma unroll
        for (int nt = 0; nt < 8; nt++)
            #pragma unroll
            for (int j = 0; j < 4; j++) s[nt][j] = 0.f;
        #pragma unroll
        for (int ks = 0; ks < 8; ks++) {
            const int kb = ks * 8;
            const int r = w * 16 + g;
            unsigned af[4];
            af[0] = Qs[r][kb + tq];     af[1] = Qs[r + 8][kb + tq];
            af[2] = Qs[r][kb + tq + 4]; af[3] = Qs[r + 8][kb + tq + 4];
            #pragma unroll
            for (int nt = 0; nt < 8; nt++) {
                int c = nt * 8 + g;
                mma8(s[nt], af, Ks[c][kb + tq], Ks[c][kb + tq + 4]);
            }
        }

        // Online softmax. Thread owns rows (16w+g): s[nt][0..1]; (16w+g+8): s[nt][2..3]
        float mx0 = -1e30f, mx1 = -1e30f;
        #pragma unroll
        for (int nt = 0; nt < 8; nt++) {
            s[nt][0] *= scale; s[nt][1] *= scale; s[nt][2] *= scale; s[nt][3] *= scale;
            mx0 = fmaxf(mx0, fmaxf(s[nt][0], s[nt][1]));
            mx1 = fmaxf(mx1, fmaxf(s[nt][2], s[nt][3]));
        }
        mx0 = fmaxf(mx0, __shfl_xor_sync(0xffffffffu, mx0, 1));
        mx0 = fmaxf(mx0, __shfl_xor_sync(0xffffffffu, mx0, 2));
        mx1 = fmaxf(mx1, __shfl_xor_sync(0xffffffffu, mx1, 1));
        mx1 = fmaxf(mx1, __shfl_xor_sync(0xffffffffu, mx1, 2));
        const float mn0 = fmaxf(m0, mx0), mn1 = fmaxf(m1, mx1);
        const float cr0 = __expf(m0 - mn0), cr1 = __expf(m1 - mn1);
        float rs0 = 0.f, rs1 = 0.f;
        #pragma unroll
        for (int nt = 0; nt < 8; nt++) {
            s[nt][0] = __expf(s[nt][0] - mn0); rs0 += s[nt][0];
            s[nt][1] = __expf(s[nt][1] - mn0); rs0 += s[nt][1];
            s[nt][2] = __expf(s[nt][2] - mn1); rs1 += s[nt][2];
            s[nt][3] = __expf(s[nt][3] - mn1); rs1 += s[nt][3];
        }
        rs0 += __shfl_xor_sync(0xffffffffu, rs0, 1);
        rs0 += __shfl_xor_sync(0xffffffffu, rs0, 2);
        rs1 += __shfl_xor_sync(0xffffffffu, rs1, 1);
        rs1 += __shfl_xor_sync(0xffffffffu, rs1, 2);
        l0 = l0 * cr0 + rs0;  l1 = l1 * cr1 + rs1;
        m0 = mn0;  m1 = mn1;
        #pragma unroll
        for (int nt = 0; nt < 8; nt++) {
            o[nt][0] *= cr0; o[nt][1] *= cr0; o[nt][2] *= cr1; o[nt][3] *= cr1;
        }

        // Store P (own 16-row strip; same-warp STS->LDS, no block sync needed)
        {
            const int pr = w * 16 + g;
            #pragma unroll
            for (int nt = 0; nt < 8; nt++) {
                const int pc = nt * 8 + 2 * tq;
                Ps[pr][pc]     = f2tf(s[nt][0]); Ps[pr][pc + 1]     = f2tf(s[nt][1]);
                Ps[pr + 8][pc] = f2tf(s[nt][2]); Ps[pr + 8][pc + 1] = f2tf(s[nt][3]);
            }
        }

        // O += P @ V   (k = 64 kv tokens, n = 64 head dims via Vt)
        #pragma unroll
        for (int ks = 0; ks < 8; ks++) {
            const int kb = ks * 8;
            const int r = w * 16 + g;
            unsigned af[4];
            af[0] = Ps[r][kb + tq];     af[1] = Ps[r + 8][kb + tq];
            af[2] = Ps[r][kb + tq + 4]; af[3] = Ps[r + 8][kb + tq + 4];
            #pragma unroll
            for (int nt = 0; nt < 8; nt++) {
                int c = nt * 8 + g;
                mma8(o[nt], af, Vt[c][kb + tq], Vt[c][kb + tq + 4]);
            }
        }
    }

    // epilogue: normalize and write (B, N, h*64 + d)
    const float inv0 = 1.f / l0, inv1 = 1.f / l1;
    const long r0 = rowbase + q0 + w * 16 + g;
    #pragma unroll
    for (int nt = 0; nt < 8; nt++) {
        const int col = h * HD + nt * 8 + 2 * tq;
        g_att[r0 * CH + col]           = o[nt][0] * inv0;
        g_att[r0 * CH + col + 1]       = o[nt][1] * inv0;
        g_att[(r0 + 8) * CH + col]     = o[nt][2] * inv1;
        g_att[(r0 + 8) * CH + col + 1] = o[nt][3] * inv1;
    }
}

// ---------------------------------------------------------------------------
extern "C" void kernel_launch(void* const* d_in, const int* in_sizes, int n_in,
                              void* d_out, int out_size)
{
    const float* x     = (const float*)d_in[0];
    const float* Wqkv  = (const float*)d_in[1];
    const float* bqkv  = (const float*)d_in[2];
    const float* Wproj = (const float*)d_in[3];
    const float* bproj = (const float*)d_in[4];
    float* out = (float*)d_out;

    float *qkv_ptr, *att_ptr;
    cudaGetSymbolAddress((void**)&qkv_ptr, g_qkv);
    cudaGetSymbolAddress((void**)&att_ptr, g_att);

    static int smem_set = 0;
    const int flash_smem = 4 * 64 * 68 * sizeof(unsigned);  // 69632 B
    if (!smem_set) {
        cudaFuncSetAttribute(flash_tf32,
                             cudaFuncAttributeMaxDynamicSharedMemorySize,
                             flash_smem);
        smem_set = 1;
    }

    // QKV projection: (8192,768) @ (768,2304) + bias
    gemm_tf32<<<dim3(C3 / 128, MTOT / 128), 256>>>(x, Wqkv, bqkv, qkv_ptr,
                                                   MTOT, C3, CH);
    // Flash attention
    flash_tf32<<<dim3(SEQ / 64, BATCH * NHEADS), 128, flash_smem>>>();
    // Output projection: (8192,768) @ (768,768) + bias
    gemm_tf32<<<dim3(CH / 128, MTOT / 128), 256>>>(att_ptr, Wproj, bproj, out,
                                                   MTOT, CH, CH);
}

// round 4
// speedup vs baseline: 5.2820x; 1.8260x over previous
#include <cuda_runtime.h>
#include <cstdint>
#include <math.h>

#define BATCH 4
#define SEQ 2048
#define CH 768
#define NHEADS 12
#define HD 64
#define MTOT (BATCH * SEQ)   // 8192
#define C3 (3 * CH)          // 2304

// Scratch (allocation-free contract)
__device__ float g_x[(size_t)MTOT * CH];       // tf32-rounded x
__device__ float g_qkv[(size_t)MTOT * C3];     // tf32-rounded qkv
__device__ float g_att[(size_t)MTOT * CH];     // tf32-rounded attn out
__device__ float g_wqkvT[(size_t)C3 * CH];     // Wqkv^T, tf32-rounded
__device__ float g_wprojT[(size_t)CH * CH];    // Wproj^T, tf32-rounded

__device__ __forceinline__ uint32_t smem_u32(const void* p) {
    uint32_t a;
    asm("{ .reg .u64 t; cvta.to.shared.u64 t, %1; cvt.u32.u64 %0, t; }"
        : "=r"(a) : "l"(p));
    return a;
}
__device__ __forceinline__ float f2tf(float x) {
    unsigned u;
    asm("cvt.rna.tf32.f32 %0, %1;" : "=r"(u) : "f"(x));
    return __uint_as_float(u);
}
#define CP16(dst, src) \
    asm volatile("cp.async.cg.shared.global [%0], [%1], 16;" \
                 :: "r"(dst), "l"(src) : "memory")
#define CP_COMMIT() asm volatile("cp.async.commit_group;" ::: "memory")
#define CP_WAIT(n)  asm volatile("cp.async.wait_group %0;" :: "n"(n) : "memory")

// m16n8k8 tf32 mma, fp32 accumulate in-place.
__device__ __forceinline__ void mma8(float* c, const unsigned* a,
                                     unsigned b0, unsigned b1) {
    asm volatile(
        "mma.sync.aligned.m16n8k8.row.col.f32.tf32.tf32.f32 "
        "{%0,%1,%2,%3}, {%4,%5,%6,%7}, {%8,%9}, {%0,%1,%2,%3};"
        : "+f"(c[0]), "+f"(c[1]), "+f"(c[2]), "+f"(c[3])
        : "r"(a[0]), "r"(a[1]), "r"(a[2]), "r"(a[3]), "r"(b0), "r"(b1));
}

// ---------------------------------------------------------------------------
// Prepass: round x to tf32 (float4 granularity; sizes divisible by 1024)
// ---------------------------------------------------------------------------
__global__ __launch_bounds__(256) void round_kernel(
    const float* __restrict__ in, float* __restrict__ outp)
{
    const int idx = blockIdx.x * 256 + threadIdx.x;
    float4 v = ((const float4*)in)[idx];
    float4 o = { f2tf(v.x), f2tf(v.y), f2tf(v.z), f2tf(v.w) };
    ((float4*)outp)[idx] = o;
}

// ---------------------------------------------------------------------------
// Weight transpose with tf32 rounding: Wt[n][k] = round(W[k][n])
// ---------------------------------------------------------------------------
__global__ __launch_bounds__(256) void transpose_kernel(
    const float* __restrict__ W, float* __restrict__ Wt, int R, int Cc)
{
    __shared__ float t[32][33];
    const int bx = blockIdx.x * 32, by = blockIdx.y * 32;
    const int x = threadIdx.x & 31, y4 = (threadIdx.x >> 5) * 4;
    #pragma unroll
    for (int j = 0; j < 4; j++)
        t[y4 + j][x] = W[(long)(by + y4 + j) * Cc + bx + x];
    __syncthreads();
    #pragma unroll
    for (int j = 0; j < 4; j++)
        Wt[(long)(bx + y4 + j) * R + by + x] = f2tf(t[x][y4 + j]);
}

// ---------------------------------------------------------------------------
// tf32 mma.sync GEMM + bias: C[M,N] = A[M,K] @ Bt[N,K]^T + bias
// 128x128 CTA tile, BK=32, 256 threads (8 warps 4x2, warp tile 32x64).
// cp.async double-buffered staging, 2 CTAs/SM. Operands pre-rounded to tf32.
// Smem stride 36 -> all fragment LDS conflict-free ((4g+tq) bank pattern).
// ---------------------------------------------------------------------------
#define GSTRIDE 36
#define GTILE (128 * GSTRIDE)

template <bool ROUND>
__global__ __launch_bounds__(256, 2) void gemm_tc(
    const float* __restrict__ A, const float* __restrict__ Bt,
    const float* __restrict__ bias, float* __restrict__ C,
    int M, int N, int K)
{
    extern __shared__ float gsm[];   // [2 bufs][A 128*36 | B 128*36]
    const int tid = threadIdx.x;
    const int lane = tid & 31, wid = tid >> 5;
    const int g = lane >> 2, tq = lane & 3;
    const int wm = (wid & 3) * 32, wn = (wid >> 2) * 64;
    const int bm = blockIdx.y * 128, bn = blockIdx.x * 128;

    const int sr = tid >> 3, sc4 = (tid & 7) * 4;   // staging: row sr+32i, col sc4

    float acc[2][8][4];
    #pragma unroll
    for (int mt = 0; mt < 2; mt++)
        #pragma unroll
        for (int nt = 0; nt < 8; nt++)
            #pragma unroll
            for (int j = 0; j < 4; j++) acc[mt][nt][j] = 0.f;

    const int NK = K / 32;

    // issue tile kt into buffer b
    auto issue = [&](int kt, int b) {
        float* As = gsm + b * 2 * GTILE;
        float* Bs = As + GTILE;
        const int k0 = kt * 32;
        #pragma unroll
        for (int i = 0; i < 4; i++) {
            int r = sr + 32 * i;
            CP16(smem_u32(As + r * GSTRIDE + sc4),
                 A + (long)(bm + r) * K + k0 + sc4);
            CP16(smem_u32(Bs + r * GSTRIDE + sc4),
                 Bt + (long)(bn + r) * K + k0 + sc4);
        }
        CP_COMMIT();
    };

    issue(0, 0);
    for (int kt = 0; kt < NK; kt++) {
        const int buf = kt & 1;
        if (kt + 1 < NK) { issue(kt + 1, buf ^ 1); CP_WAIT(1); }
        else             { CP_WAIT(0); }
        __syncthreads();

        const unsigned* As = (const unsigned*)(gsm + buf * 2 * GTILE);
        const unsigned* Bs = As + GTILE;
        #pragma unroll
        for (int ks = 0; ks < 4; ks++) {
            const int kb = ks * 8;
            unsigned af[2][4];
            #pragma unroll
            for (int mt = 0; mt < 2; mt++) {
                int r = wm + mt * 16 + g;
                af[mt][0] = As[r * GSTRIDE + kb + tq];
                af[mt][1] = As[(r + 8) * GSTRIDE + kb + tq];
                af[mt][2] = As[r * GSTRIDE + kb + tq + 4];
                af[mt][3] = As[(r + 8) * GSTRIDE + kb + tq + 4];
            }
            #pragma unroll
            for (int nt = 0; nt < 8; nt++) {
                int c = wn + nt * 8 + g;
                unsigned b0 = Bs[c * GSTRIDE + kb + tq];
                unsigned b1 = Bs[c * GSTRIDE + kb + tq + 4];
                mma8(acc[0][nt], af[0], b0, b1);
                mma8(acc[1][nt], af[1], b0, b1);
            }
        }
        __syncthreads();
    }

    // Epilogue: bias add (+ optional tf32 rounding), float2 stores
    #pragma unroll
    for (int mt = 0; mt < 2; mt++) {
        const long r0 = bm + wm + mt * 16 + g;
        #pragma unroll
        for (int nt = 0; nt < 8; nt++) {
            const int col = bn + wn + nt * 8 + 2 * tq;
            const float bz0 = bias[col], bz1 = bias[col + 1];
            float2 v0 = { acc[mt][nt][0] + bz0, acc[mt][nt][1] + bz1 };
            float2 v1 = { acc[mt][nt][2] + bz0, acc[mt][nt][3] + bz1 };
            if (ROUND) {
                v0.x = f2tf(v0.x); v0.y = f2tf(v0.y);
                v1.x = f2tf(v1.x); v1.y = f2tf(v1.y);
            }
            *(float2*)(C + r0 * N + col)       = v0;
            *(float2*)(C + (r0 + 8) * N + col) = v1;
        }
    }
}

// ---------------------------------------------------------------------------
// Flash attention, tf32 mma.sync. Br=128, Bc=64, 128 threads (4 warps),
// 2 CTAs/SM. Warp w owns rows [32w, 32w+32). Scale folded into Q staging.
// Smem pads: Qs/Ps stride 68 (A-frag pattern), Ks 68 (Bt pattern),
// Vs 72 (B pattern) -> every fragment LDS conflict-free.
// K/V staged via cp.async (operands pre-rounded in g_qkv).
// ---------------------------------------------------------------------------
#define QS_OFF 0
#define PS_OFF (128 * 68)
#define KS_OFF (2 * 128 * 68)
#define VS_OFF (2 * 128 * 68 + 64 * 68)
#define FL_WORDS (2 * 128 * 68 + 64 * 68 + 64 * 72)   // 26368 words = 105472 B

__global__ __launch_bounds__(128, 2) void flash_tf32()
{
    extern __shared__ float sm[];
    float* Qs = sm + QS_OFF;
    float* Ps = sm + PS_OFF;
    float* Ks = sm + KS_OFF;
    float* Vs = sm + VS_OFF;

    const int tid = threadIdx.x;
    const int lane = tid & 31, w = tid >> 5;
    const int g = lane >> 2, tq = lane & 3;
    const int b = blockIdx.y / NHEADS, h = blockIdx.y % NHEADS;
    const int q0 = blockIdx.x * 128;
    const long rowbase = (long)b * SEQ;

    // Load Q tile, folding 1/sqrt(d)=0.125 (exact power of two -> stays tf32)
    #pragma unroll
    for (int i = 0; i < 16; i++) {
        int idx = tid + 128 * i;
        int r = idx >> 4, c4 = (idx & 15) * 4;
        float4 v = *(const float4*)&g_qkv[(rowbase + q0 + r) * C3 + h * HD + c4];
        float* d = Qs + r * 68 + c4;
        d[0] = v.x * 0.125f; d[1] = v.y * 0.125f;
        d[2] = v.z * 0.125f; d[3] = v.w * 0.125f;
    }

    float o[2][8][4];
    float m_i[2][2], l_i[2][2];
    #pragma unroll
    for (int mt = 0; mt < 2; mt++) {
        m_i[mt][0] = m_i[mt][1] = -1e30f;
        l_i[mt][0] = l_i[mt][1] = 0.f;
        #pragma unroll
        for (int nt = 0; nt < 8; nt++)
            #pragma unroll
            for (int j = 0; j < 4; j++) o[mt][nt][j] = 0.f;
    }

    for (int k0 = 0; k0 < SEQ; k0 += 64) {
        __syncthreads();   // prev tile's reads done; Q staged (first iter)
        #pragma unroll
        for (int i = 0; i < 8; i++) {
            int idx = tid + 128 * i;
            int r = idx >> 4, c4 = (idx & 15) * 4;
            long gb = (rowbase + k0 + r) * C3 + h * HD + c4;
            CP16(smem_u32(Ks + r * 68 + c4), &g_qkv[gb + CH]);
            CP16(smem_u32(Vs + r * 72 + c4), &g_qkv[gb + 2 * CH]);
        }
        CP_COMMIT();
        CP_WAIT(0);
        __syncthreads();

        // S = Q @ K^T : warp rows [32w, 32w+32), 64 kv cols
        float s[2][8][4];
        #pragma unroll
        for (int mt = 0; mt < 2; mt++)
            #pragma unroll
            for (int nt = 0; nt < 8; nt++)
                #pragma unroll
                for (int j = 0; j < 4; j++) s[mt][nt][j] = 0.f;
        const unsigned* Qu = (const unsigned*)Qs;
        const unsigned* Ku = (const unsigned*)Ks;
        #pragma unroll
        for (int ks = 0; ks < 8; ks++) {
            const int kb = ks * 8;
            unsigned af[2][4];
            #pragma unroll
            for (int mt = 0; mt < 2; mt++) {
                int rr = w * 32 + mt * 16 + g;
                af[mt][0] = Qu[rr * 68 + kb + tq];
                af[mt][1] = Qu[(rr + 8) * 68 + kb + tq];
                af[mt][2] = Qu[rr * 68 + kb + tq + 4];
                af[mt][3] = Qu[(rr + 8) * 68 + kb + tq + 4];
            }
            #pragma unroll
            for (int nt = 0; nt < 8; nt++) {
                int c = nt * 8 + g;
                unsigned b0 = Ku[c * 68 + kb + tq];
                unsigned b1 = Ku[c * 68 + kb + tq + 4];
                mma8(s[0][nt], af[0], b0, b1);
                mma8(s[1][nt], af[1], b0, b1);
            }
        }

        // Online softmax per 16-row sub-tile
        #pragma unroll
        for (int mt = 0; mt < 2; mt++) {
            float mx0 = -1e30f, mx1 = -1e30f;
            #pragma unroll
            for (int nt = 0; nt < 8; nt++) {
                mx0 = fmaxf(mx0, fmaxf(s[mt][nt][0], s[mt][nt][1]));
                mx1 = fmaxf(mx1, fmaxf(s[mt][nt][2], s[mt][nt][3]));
            }
            mx0 = fmaxf(mx0, __shfl_xor_sync(0xffffffffu, mx0, 1));
            mx0 = fmaxf(mx0, __shfl_xor_sync(0xffffffffu, mx0, 2));
            mx1 = fmaxf(mx1, __shfl_xor_sync(0xffffffffu, mx1, 1));
            mx1 = fmaxf(mx1, __shfl_xor_sync(0xffffffffu, mx1, 2));
            const float mn0 = fmaxf(m_i[mt][0], mx0), mn1 = fmaxf(m_i[mt][1], mx1);
            const float cr0 = __expf(m_i[mt][0] - mn0), cr1 = __expf(m_i[mt][1] - mn1);
            float rs0 = 0.f, rs1 = 0.f;
            #pragma unroll
            for (int nt = 0; nt < 8; nt++) {
                s[mt][nt][0] = __expf(s[mt][nt][0] - mn0); rs0 += s[mt][nt][0];
                s[mt][nt][1] = __expf(s[mt][nt][1] - mn0); rs0 += s[mt][nt][1];
                s[mt][nt][2] = __expf(s[mt][nt][2] - mn1); rs1 += s[mt][nt][2];
                s[mt][nt][3] = __expf(s[mt][nt][3] - mn1); rs1 += s[mt][nt][3];
            }
            rs0 += __shfl_xor_sync(0xffffffffu, rs0, 1);
            rs0 += __shfl_xor_sync(0xffffffffu, rs0, 2);
            rs1 += __shfl_xor_sync(0xffffffffu, rs1, 1);
            rs1 += __shfl_xor_sync(0xffffffffu, rs1, 2);
            l_i[mt][0] = l_i[mt][0] * cr0 + rs0;
            l_i[mt][1] = l_i[mt][1] * cr1 + rs1;
            m_i[mt][0] = mn0; m_i[mt][1] = mn1;
            #pragma unroll
            for (int nt = 0; nt < 8; nt++) {
                o[mt][nt][0] *= cr0; o[mt][nt][1] *= cr0;
                o[mt][nt][2] *= cr1; o[mt][nt][3] *= cr1;
            }
            // Store P (warp-private strip), tf32-rounded
            const int pr = w * 32 + mt * 16 + g;
            #pragma unroll
            for (int nt = 0; nt < 8; nt++) {
                const int pc = nt * 8 + 2 * tq;
                Ps[pr * 68 + pc]           = f2tf(s[mt][nt][0]);
                Ps[pr * 68 + pc + 1]       = f2tf(s[mt][nt][1]);
                Ps[(pr + 8) * 68 + pc]     = f2tf(s[mt][nt][2]);
                Ps[(pr + 8) * 68 + pc + 1] = f2tf(s[mt][nt][3]);
            }
        }
        __syncwarp();

        // O += P @ V
        const unsigned* Pu = (const unsigned*)Ps;
        const unsigned* Vu = (const unsigned*)Vs;
        #pragma unroll
        for (int ks = 0; ks < 8; ks++) {
            const int kb = ks * 8;
            unsigned af[2][4];
            #pragma unroll
            for (int mt = 0; mt < 2; mt++) {
                int rr = w * 32 + mt * 16 + g;
                af[mt][0] = Pu[rr * 68 + kb + tq];
                af[mt][1] = Pu[(rr + 8) * 68 + kb + tq];
                af[mt][2] = Pu[rr * 68 + kb + tq + 4];
                af[mt][3] = Pu[(rr + 8) * 68 + kb + tq + 4];
            }
            #pragma unroll
            for (int nt = 0; nt < 8; nt++) {
                int c = nt * 8 + g;
                unsigned b0 = Vu[(kb + tq) * 72 + c];
                unsigned b1 = Vu[(kb + tq + 4) * 72 + c];
                mma8(o[0][nt], af[0], b0, b1);
                mma8(o[1][nt], af[1], b0, b1);
            }
        }
    }

    // Epilogue: normalize, round to tf32 (feeds proj GEMM), write
    #pragma unroll
    for (int mt = 0; mt < 2; mt++) {
        const float inv0 = 1.f / l_i[mt][0], inv1 = 1.f / l_i[mt][1];
        const long r0 = rowbase + q0 + w * 32 + mt * 16 + g;
        #pragma unroll
        for (int nt = 0; nt < 8; nt++) {
            const int col = h * HD + nt * 8 + 2 * tq;
            float2 v0 = { f2tf(o[mt][nt][0] * inv0), f2tf(o[mt][nt][1] * inv0) };
            float2 v1 = { f2tf(o[mt][nt][2] * inv1), f2tf(o[mt][nt][3] * inv1) };
            *(float2*)(g_att + r0 * CH + col)       = v0;
            *(float2*)(g_att + (r0 + 8) * CH + col) = v1;
        }
    }
}

// ---------------------------------------------------------------------------
extern "C" void kernel_launch(void* const* d_in, const int* in_sizes, int n_in,
                              void* d_out, int out_size)
{
    const float* x     = (const float*)d_in[0];
    const float* Wqkv  = (const float*)d_in[1];
    const float* bqkv  = (const float*)d_in[2];
    const float* Wproj = (const float*)d_in[3];
    const float* bproj = (const float*)d_in[4];
    float* out = (float*)d_out;

    float *xr, *qkv_ptr, *att_ptr, *wqkvT, *wprojT;
    cudaGetSymbolAddress((void**)&xr, g_x);
    cudaGetSymbolAddress((void**)&qkv_ptr, g_qkv);
    cudaGetSymbolAddress((void**)&att_ptr, g_att);
    cudaGetSymbolAddress((void**)&wqkvT, g_wqkvT);
    cudaGetSymbolAddress((void**)&wprojT, g_wprojT);

    static int smem_set = 0;
    const int gemm_smem  = 4 * GTILE * sizeof(float);     // 73728 B
    const int flash_smem = FL_WORDS * sizeof(float);      // 105472 B
    if (!smem_set) {
        cudaFuncSetAttribute(gemm_tc<true>,
            cudaFuncAttributeMaxDynamicSharedMemorySize, gemm_smem);
        cudaFuncSetAttribute(gemm_tc<false>,
            cudaFuncAttributeMaxDynamicSharedMemorySize, gemm_smem);
        cudaFuncSetAttribute(flash_tf32,
            cudaFuncAttributeMaxDynamicSharedMemorySize, flash_smem);
        smem_set = 1;
    }

    // Pre-round x; transpose + round weights
    round_kernel<<<(MTOT * CH) / 1024, 256>>>(x, xr);
    transpose_kernel<<<dim3(C3 / 32, CH / 32), 256>>>(Wqkv, wqkvT, CH, C3);
    transpose_kernel<<<dim3(CH / 32, CH / 32), 256>>>(Wproj, wprojT, CH, CH);

    // QKV projection (output tf32-rounded -> feeds flash raw)
    gemm_tc<true><<<dim3(C3 / 128, MTOT / 128), 256, gemm_smem>>>(
        xr, wqkvT, bqkv, qkv_ptr, MTOT, C3, CH);
    // Flash attention
    flash_tf32<<<dim3(SEQ / 128, BATCH * NHEADS), 128, flash_smem>>>();
    // Output projection (full fp32 output)
    gemm_tc<false><<<dim3(CH / 128, MTOT / 128), 256, gemm_smem>>>(
        att_ptr, wprojT, bproj, out, MTOT, CH, CH);
}